// round 1
// baseline (speedup 1.0000x reference)
#include <cuda_runtime.h>
#include <cuda_bf16.h>
#include <math.h>

// Problem constants
#define TB 32      // batch
#define TS 512     // seq len
#define TE 512     // d_model
#define THD 64     // head dim
#define TNH 8      // heads
#define TL 3       // layers
#define TT (TB*TS) // tokens = 16384
#define QKVW 1536  // 3*E

// Scratch (device globals; allocation-free contract)
__device__ float g_x[(size_t)TT * TE];       // running hidden   32 MB
__device__ float g_qkv[(size_t)TT * QKVW];   // qkv              96 MB
__device__ float g_att[(size_t)TT * TE];     // attn concat out  32 MB
__device__ float g_y[(size_t)TT * TE];       // gemm out         32 MB
__device__ float g_h[(size_t)TT * 4 * TE];   // ffn hidden      128 MB

// ---------------------------------------------------------------------------
// Embedding: x[t] = emb[ids[t]] + pos[t % S]
// ---------------------------------------------------------------------------
__global__ __launch_bounds__(256) void embed_kernel(
    const int* __restrict__ ids, const float* __restrict__ emb,
    const float* __restrict__ pos, float* __restrict__ x) {
    int idx = blockIdx.x * blockDim.x + threadIdx.x;      // over TT*128 float4s
    int token = idx >> 7;
    int c = idx & 127;
    float4 e = reinterpret_cast<const float4*>(emb)[(size_t)ids[token] * 128 + c];
    float4 p = reinterpret_cast<const float4*>(pos)[(size_t)(token & (TS - 1)) * 128 + c];
    float4 o;
    o.x = e.x + p.x; o.y = e.y + p.y; o.z = e.z + p.z; o.w = e.w + p.w;
    reinterpret_cast<float4*>(x)[idx] = o;
}

// ---------------------------------------------------------------------------
// SGEMM: C[M,N] = A[M,K] @ W[N,K]^T + bias[N], optional exact GELU.
// Block tile 128x128, Ktile 8, 256 threads, 8x8 per thread.
// Requires M%128==0, N%128==0, K%8==0 (true for all uses).
// ---------------------------------------------------------------------------
template <int ACT>
__global__ __launch_bounds__(256) void sgemm_kernel(
    const float* __restrict__ A, const float* __restrict__ W,
    const float* __restrict__ bias, float* __restrict__ C,
    int N, int K) {
    __shared__ float As[8][128];
    __shared__ float Bs[8][128];
    const int t = threadIdx.x;
    const int tx = t & 15, ty = t >> 4;
    const int lrow = t >> 1;            // 0..127
    const int lq = (t & 1) << 2;        // 0 or 4
    const float* Ap = A + (size_t)(blockIdx.y * 128 + lrow) * K + lq;
    const float* Wp = W + (size_t)(blockIdx.x * 128 + lrow) * K + lq;
    float c[8][8];
#pragma unroll
    for (int i = 0; i < 8; i++)
#pragma unroll
        for (int j = 0; j < 8; j++) c[i][j] = 0.f;

    for (int k0 = 0; k0 < K; k0 += 8) {
        float4 a4 = *reinterpret_cast<const float4*>(Ap + k0);
        float4 b4 = *reinterpret_cast<const float4*>(Wp + k0);
        __syncthreads();
        As[lq + 0][lrow] = a4.x; As[lq + 1][lrow] = a4.y;
        As[lq + 2][lrow] = a4.z; As[lq + 3][lrow] = a4.w;
        Bs[lq + 0][lrow] = b4.x; Bs[lq + 1][lrow] = b4.y;
        Bs[lq + 2][lrow] = b4.z; Bs[lq + 3][lrow] = b4.w;
        __syncthreads();
#pragma unroll
        for (int kk = 0; kk < 8; kk++) {
            float ar[8], br[8];
#pragma unroll
            for (int i = 0; i < 8; i++) ar[i] = As[kk][ty * 8 + i];
#pragma unroll
            for (int j = 0; j < 8; j++) br[j] = Bs[kk][tx * 8 + j];
#pragma unroll
            for (int i = 0; i < 8; i++)
#pragma unroll
                for (int j = 0; j < 8; j++) c[i][j] = fmaf(ar[i], br[j], c[i][j]);
        }
    }
#pragma unroll
    for (int i = 0; i < 8; i++) {
        size_t row = (size_t)blockIdx.y * 128 + ty * 8 + i;
#pragma unroll
        for (int j = 0; j < 8; j++) {
            int col = blockIdx.x * 128 + tx * 8 + j;
            float v = c[i][j] + bias[col];
            if (ACT == 1) v = 0.5f * v * (1.f + erff(v * 0.70710678118654752f));
            C[row * N + col] = v;
        }
    }
}

// ---------------------------------------------------------------------------
// Attention scores: per (b,h): S_out = scale * Q K^T + mask_bias
// Tiles 64x64, K=64. Writes into the attns output region (pre-softmax).
// grid (8 ntile, 8 mtile, B*NH), block 256 (16x16, 4x4 per thread)
// ---------------------------------------------------------------------------
__global__ __launch_bounds__(256) void attn_scores_kernel(
    const float* __restrict__ qkv, const int* __restrict__ mask,
    float* __restrict__ attn) {
    const int bh = blockIdx.z, b = bh >> 3, h = bh & 7;
    const float* qb = qkv + (size_t)b * TS * QKVW + h * THD;
    const float* kb = qb + TE;  // k block offset
    __shared__ float Qs[16][64];
    __shared__ float Ks[16][64];
    const int t = threadIdx.x, tx = t & 15, ty = t >> 4;
    const int lrow = t >> 2;          // 0..63
    const int lq = (t & 3) << 2;      // 0,4,8,12
    const int m0 = blockIdx.y * 64, n0 = blockIdx.x * 64;
    float c[4][4] = {};
    for (int k0 = 0; k0 < THD; k0 += 16) {
        float4 q4 = *reinterpret_cast<const float4*>(qb + (size_t)(m0 + lrow) * QKVW + k0 + lq);
        float4 k4 = *reinterpret_cast<const float4*>(kb + (size_t)(n0 + lrow) * QKVW + k0 + lq);
        __syncthreads();
        Qs[lq + 0][lrow] = q4.x; Qs[lq + 1][lrow] = q4.y;
        Qs[lq + 2][lrow] = q4.z; Qs[lq + 3][lrow] = q4.w;
        Ks[lq + 0][lrow] = k4.x; Ks[lq + 1][lrow] = k4.y;
        Ks[lq + 2][lrow] = k4.z; Ks[lq + 3][lrow] = k4.w;
        __syncthreads();
#pragma unroll
        for (int kk = 0; kk < 16; kk++) {
            float ar[4], br[4];
#pragma unroll
            for (int i = 0; i < 4; i++) ar[i] = Qs[kk][ty * 4 + i];
#pragma unroll
            for (int j = 0; j < 4; j++) br[j] = Ks[kk][tx * 4 + j];
#pragma unroll
            for (int i = 0; i < 4; i++)
#pragma unroll
                for (int j = 0; j < 4; j++) c[i][j] = fmaf(ar[i], br[j], c[i][j]);
        }
    }
    float* out = attn + (size_t)bh * TS * TS;
    const float scale = 0.125f;  // 1/sqrt(64)
#pragma unroll
    for (int i = 0; i < 4; i++) {
        int qi = m0 + ty * 4 + i;
#pragma unroll
        for (int j = 0; j < 4; j++) {
            int kj = n0 + tx * 4 + j;
            float mb = (mask[b * TS + kj] == 0) ? -1e30f : 0.f;
            out[(size_t)qi * TS + kj] = c[i][j] * scale + mb;
        }
    }
}

// ---------------------------------------------------------------------------
// Row softmax in-place over 512 keys. 1 block/row, 128 threads, float4.
// ---------------------------------------------------------------------------
__global__ __launch_bounds__(128) void softmax_kernel(float* __restrict__ attn) {
    float* row = attn + (size_t)blockIdx.x * TS;
    const int t = threadIdx.x;
    float4 v = reinterpret_cast<float4*>(row)[t];
    float m = fmaxf(fmaxf(v.x, v.y), fmaxf(v.z, v.w));
#pragma unroll
    for (int o = 16; o; o >>= 1) m = fmaxf(m, __shfl_xor_sync(0xFFFFFFFFu, m, o));
    __shared__ float sm[4], ss[4];
    if ((t & 31) == 0) sm[t >> 5] = m;
    __syncthreads();
    m = fmaxf(fmaxf(sm[0], sm[1]), fmaxf(sm[2], sm[3]));
    v.x = __expf(v.x - m); v.y = __expf(v.y - m);
    v.z = __expf(v.z - m); v.w = __expf(v.w - m);
    float s = v.x + v.y + v.z + v.w;
#pragma unroll
    for (int o = 16; o; o >>= 1) s += __shfl_xor_sync(0xFFFFFFFFu, s, o);
    if ((t & 31) == 0) ss[t >> 5] = s;
    __syncthreads();
    s = ss[0] + ss[1] + ss[2] + ss[3];
    float inv = 1.f / s;
    v.x *= inv; v.y *= inv; v.z *= inv; v.w *= inv;
    reinterpret_cast<float4*>(row)[t] = v;
}

// ---------------------------------------------------------------------------
// AV: per (b,h): O[S,64] = P[S,S] @ V[S,64], scattered to concat layout.
// grid (8 mtile, B*NH), block 256 (16x16, 4x4), Ktile 16.
// ---------------------------------------------------------------------------
__global__ __launch_bounds__(256) void attn_av_kernel(
    const float* __restrict__ attn, const float* __restrict__ qkv,
    float* __restrict__ outx) {
    const int bh = blockIdx.y, b = bh >> 3, h = bh & 7;
    const float* P = attn + (size_t)bh * TS * TS;
    const float* vb = qkv + (size_t)b * TS * QKVW + 2 * TE + h * THD;
    __shared__ float Ps[16][64];
    __shared__ float Vs[16][64];
    const int t = threadIdx.x, tx = t & 15, ty = t >> 4;
    const int m0 = blockIdx.x * 64;
    const int prow = t >> 2, pq = (t & 3) << 2;     // P: 64 rows x 16 k
    const int vrow = t >> 4, vq = (t & 15) << 2;    // V: 16 rows x 64 d
    float c[4][4] = {};
    for (int k0 = 0; k0 < TS; k0 += 16) {
        float4 p4 = *reinterpret_cast<const float4*>(P + (size_t)(m0 + prow) * TS + k0 + pq);
        float4 v4 = *reinterpret_cast<const float4*>(vb + (size_t)(k0 + vrow) * QKVW + vq);
        __syncthreads();
        Ps[pq + 0][prow] = p4.x; Ps[pq + 1][prow] = p4.y;
        Ps[pq + 2][prow] = p4.z; Ps[pq + 3][prow] = p4.w;
        Vs[vrow][vq + 0] = v4.x; Vs[vrow][vq + 1] = v4.y;
        Vs[vrow][vq + 2] = v4.z; Vs[vrow][vq + 3] = v4.w;
        __syncthreads();
#pragma unroll
        for (int kk = 0; kk < 16; kk++) {
            float ar[4], br[4];
#pragma unroll
            for (int i = 0; i < 4; i++) ar[i] = Ps[kk][ty * 4 + i];
#pragma unroll
            for (int j = 0; j < 4; j++) br[j] = Vs[kk][tx * 4 + j];
#pragma unroll
            for (int i = 0; i < 4; i++)
#pragma unroll
                for (int j = 0; j < 4; j++) c[i][j] = fmaf(ar[i], br[j], c[i][j]);
        }
    }
#pragma unroll
    for (int i = 0; i < 4; i++) {
        int qi = m0 + ty * 4 + i;
        float* o = outx + ((size_t)b * TS + qi) * TE + h * THD + tx * 4;
#pragma unroll
        for (int j = 0; j < 4; j++) o[j] = c[i][j];
    }
}

// ---------------------------------------------------------------------------
// Fused residual + LayerNorm: x = LN(x + y) * g + b. 1 block/token, 128 thr.
// ---------------------------------------------------------------------------
__global__ __launch_bounds__(128) void add_ln_kernel(
    float* __restrict__ x, const float* __restrict__ y,
    const float* __restrict__ g, const float* __restrict__ bb) {
    const size_t row = blockIdx.x;
    const int t = threadIdx.x;
    float4 xv = reinterpret_cast<float4*>(x + row * TE)[t];
    float4 yv = reinterpret_cast<const float4*>(y + row * TE)[t];
    float4 s;
    s.x = xv.x + yv.x; s.y = xv.y + yv.y; s.z = xv.z + yv.z; s.w = xv.w + yv.w;
    float sum = s.x + s.y + s.z + s.w;
    float sq = s.x * s.x + s.y * s.y + s.z * s.z + s.w * s.w;
#pragma unroll
    for (int o = 16; o; o >>= 1) {
        sum += __shfl_xor_sync(0xFFFFFFFFu, sum, o);
        sq  += __shfl_xor_sync(0xFFFFFFFFu, sq, o);
    }
    __shared__ float s1[4], s2[4];
    if ((t & 31) == 0) { s1[t >> 5] = sum; s2[t >> 5] = sq; }
    __syncthreads();
    sum = s1[0] + s1[1] + s1[2] + s1[3];
    sq  = s2[0] + s2[1] + s2[2] + s2[3];
    const float mean = sum * (1.f / TE);
    const float var = sq * (1.f / TE) - mean * mean;
    const float rstd = rsqrtf(var + 1e-5f);
    float4 gv = reinterpret_cast<const float4*>(g)[t];
    float4 bv = reinterpret_cast<const float4*>(bb)[t];
    float4 o;
    o.x = (s.x - mean) * rstd * gv.x + bv.x;
    o.y = (s.y - mean) * rstd * gv.y + bv.y;
    o.z = (s.z - mean) * rstd * gv.z + bv.z;
    o.w = (s.w - mean) * rstd * gv.w + bv.w;
    reinterpret_cast<float4*>(x + row * TE)[t] = o;
}

// ---------------------------------------------------------------------------
// CLS head: logits[b][c] = x[b*S] . cls_w[c] + cls_b[c]
// ---------------------------------------------------------------------------
__global__ void cls_kernel(const float* __restrict__ x, const float* __restrict__ w,
                           const float* __restrict__ cb, float* __restrict__ out) {
    int t = threadIdx.x;
    if (t >= TB * 2) return;
    int b = t >> 1, c = t & 1;
    const float* xr = x + (size_t)b * TS * TE;
    const float* wr = w + c * TE;
    float s = cb[c];
    for (int e = 0; e < TE; e++) s = fmaf(xr[e], wr[e], s);
    out[b * 2 + c] = s;
}

// ---------------------------------------------------------------------------
extern "C" void kernel_launch(void* const* d_in, const int* in_sizes, int n_in,
                              void* d_out, int out_size) {
    const int*   ids  = (const int*)d_in[0];
    const int*   mask = (const int*)d_in[1];
    const float* emb  = (const float*)d_in[2];
    const float* pos  = (const float*)d_in[3];
    const float* ipw  = (const float*)d_in[4];
    const float* ipb  = (const float*)d_in[5];
    const float* opw  = (const float*)d_in[6];
    const float* opb  = (const float*)d_in[7];
    const float* l1g  = (const float*)d_in[8];
    const float* l1b  = (const float*)d_in[9];
    const float* l2g  = (const float*)d_in[10];
    const float* l2b  = (const float*)d_in[11];
    const float* f1w  = (const float*)d_in[12];
    const float* f1b  = (const float*)d_in[13];
    const float* f2w  = (const float*)d_in[14];
    const float* f2b  = (const float*)d_in[15];
    const float* cw   = (const float*)d_in[16];
    const float* cb   = (const float*)d_in[17];
    float* out = (float*)d_out;
    float* attn_base = out + TB * 2;  // logits first, then [L,B,NH,S,S] attn

    float *x, *qkv, *att, *y, *hb;
    cudaGetSymbolAddress((void**)&x,   g_x);
    cudaGetSymbolAddress((void**)&qkv, g_qkv);
    cudaGetSymbolAddress((void**)&att, g_att);
    cudaGetSymbolAddress((void**)&y,   g_y);
    cudaGetSymbolAddress((void**)&hb,  g_h);

    embed_kernel<<<(TT * 128) / 256, 256>>>(ids, emb, pos, x);

    for (int l = 0; l < TL; l++) {
        // QKV projection: [TT,1536]
        sgemm_kernel<0><<<dim3(QKVW / 128, TT / 128), 256>>>(
            x, ipw + (size_t)l * QKVW * TE, ipb + l * QKVW, qkv, QKVW, TE);

        float* attn_l = attn_base + (size_t)l * TB * TNH * TS * TS;
        attn_scores_kernel<<<dim3(8, 8, TB * TNH), 256>>>(qkv, mask, attn_l);
        softmax_kernel<<<TB * TNH * TS, 128>>>(attn_l);
        attn_av_kernel<<<dim3(8, TB * TNH), 256>>>(attn_l, qkv, att);

        // out projection
        sgemm_kernel<0><<<dim3(TE / 128, TT / 128), 256>>>(
            att, opw + (size_t)l * TE * TE, opb + l * TE, y, TE, TE);
        add_ln_kernel<<<TT, 128>>>(x, y, l1g + l * TE, l1b + l * TE);

        // FFN
        sgemm_kernel<1><<<dim3(4 * TE / 128, TT / 128), 256>>>(
            x, f1w + (size_t)l * 4 * TE * TE, f1b + l * 4 * TE, hb, 4 * TE, TE);
        sgemm_kernel<0><<<dim3(TE / 128, TT / 128), 256>>>(
            hb, f2w + (size_t)l * TE * 4 * TE, f2b + l * TE, y, TE, 4 * TE);
        add_ln_kernel<<<TT, 128>>>(x, y, l2g + l * TE, l2b + l * TE);
    }

    cls_kernel<<<1, 64>>>(x, cw, cb, out);
}

// round 2
// speedup vs baseline: 2.1705x; 2.1705x over previous
#include <cuda_runtime.h>
#include <cuda_bf16.h>
#include <cstdint>
#include <math.h>

// Problem constants
#define TB 32      // batch
#define TS 512     // seq len
#define TE 512     // d_model
#define THD 64     // head dim
#define TNH 8      // heads
#define TL 3       // layers
#define TT (TB*TS) // tokens = 16384
#define QKVW 1536  // 3*E

// Scratch (device globals; allocation-free contract)
__device__ float g_x[(size_t)TT * TE];       // running hidden   32 MB
__device__ float g_qkv[(size_t)TT * QKVW];   // qkv              96 MB
__device__ float g_att[(size_t)TT * TE];     // attn concat out  32 MB
__device__ float g_y[(size_t)TT * TE];       // gemm out         32 MB
__device__ float g_h[(size_t)TT * 4 * TE];   // ffn hidden      128 MB

// ---------------------------------------------------------------------------
// Embedding: x[t] = emb[ids[t]] + pos[t % S]
// ---------------------------------------------------------------------------
__global__ __launch_bounds__(256) void embed_kernel(
    const int* __restrict__ ids, const float* __restrict__ emb,
    const float* __restrict__ pos, float* __restrict__ x) {
    int idx = blockIdx.x * blockDim.x + threadIdx.x;      // over TT*128 float4s
    int token = idx >> 7;
    int c = idx & 127;
    float4 e = reinterpret_cast<const float4*>(emb)[(size_t)ids[token] * 128 + c];
    float4 p = reinterpret_cast<const float4*>(pos)[(size_t)(token & (TS - 1)) * 128 + c];
    float4 o;
    o.x = e.x + p.x; o.y = e.y + p.y; o.z = e.z + p.z; o.w = e.w + p.w;
    reinterpret_cast<float4*>(x)[idx] = o;
}

// ---------------------------------------------------------------------------
// TF32 tensor-core GEMM: C[M,N] = A[M,K] @ W[N,K]^T + bias[N], optional GELU.
// Block tile 128x128, ktile 32, 256 threads = 8 warps, warp tile 64x32.
// mma.sync.aligned.m16n8k8.row.col.f32.tf32.tf32.f32
// Requires M%128==0, N%128==0, K%32==0 (true for all uses here).
// Smem pitch 36 -> conflict-free fragment loads.
// ---------------------------------------------------------------------------
#define SPITCH 36

__device__ __forceinline__ uint32_t f2tf32(float x) {
    uint32_t u;
    asm("cvt.rna.tf32.f32 %0, %1;" : "=r"(u) : "f"(x));
    return u;
}

template <int ACT>
__global__ __launch_bounds__(256) void tgemm_kernel(
    const float* __restrict__ A, const float* __restrict__ W,
    const float* __restrict__ bias, float* __restrict__ C,
    int N, int K) {
    __shared__ uint32_t As[128 * SPITCH];
    __shared__ uint32_t Ws[128 * SPITCH];

    const int t = threadIdx.x;
    const int lane = t & 31;
    const int warp = t >> 5;
    const int wr = (warp >> 2) * 64;   // warp row offset within block tile
    const int wc = (warp & 3) * 32;    // warp col offset
    const int qr = lane >> 2;          // 0..7
    const int qc = lane & 3;           // 0..3

    const int m0 = blockIdx.y * 128;
    const int n0 = blockIdx.x * 128;

    float acc[4][4][4];
#pragma unroll
    for (int i = 0; i < 4; i++)
#pragma unroll
        for (int j = 0; j < 4; j++)
#pragma unroll
            for (int r = 0; r < 4; r++) acc[i][j][r] = 0.f;

    // each thread loads 4 float4 of A and 4 float4 of W per ktile
    // f4idx = t + 256*i : row = f4idx>>3 (0..127), kq = f4idx&7
    for (int k0 = 0; k0 < K; k0 += 32) {
        float4 av[4], wv[4];
#pragma unroll
        for (int i = 0; i < 4; i++) {
            int f4 = t + 256 * i;
            int row = f4 >> 3, kq = f4 & 7;
            av[i] = *reinterpret_cast<const float4*>(A + (size_t)(m0 + row) * K + k0 + kq * 4);
            wv[i] = *reinterpret_cast<const float4*>(W + (size_t)(n0 + row) * K + k0 + kq * 4);
        }
        __syncthreads();
#pragma unroll
        for (int i = 0; i < 4; i++) {
            int f4 = t + 256 * i;
            int row = f4 >> 3, kq = f4 & 7;
            uint32_t* as = &As[row * SPITCH + kq * 4];
            as[0] = f2tf32(av[i].x); as[1] = f2tf32(av[i].y);
            as[2] = f2tf32(av[i].z); as[3] = f2tf32(av[i].w);
            uint32_t* ws = &Ws[row * SPITCH + kq * 4];
            ws[0] = f2tf32(wv[i].x); ws[1] = f2tf32(wv[i].y);
            ws[2] = f2tf32(wv[i].z); ws[3] = f2tf32(wv[i].w);
        }
        __syncthreads();

#pragma unroll
        for (int kk = 0; kk < 32; kk += 8) {
            uint32_t a[4][4], b[4][2];
#pragma unroll
            for (int mi = 0; mi < 4; mi++) {
                const uint32_t* base = &As[(wr + mi * 16 + qr) * SPITCH + kk + qc];
                a[mi][0] = base[0];
                a[mi][1] = base[8 * SPITCH];
                a[mi][2] = base[4];
                a[mi][3] = base[8 * SPITCH + 4];
            }
#pragma unroll
            for (int ni = 0; ni < 4; ni++) {
                const uint32_t* base = &Ws[(wc + ni * 8 + qr) * SPITCH + kk + qc];
                b[ni][0] = base[0];
                b[ni][1] = base[4];
            }
#pragma unroll
            for (int mi = 0; mi < 4; mi++)
#pragma unroll
                for (int ni = 0; ni < 4; ni++) {
                    asm volatile(
                        "mma.sync.aligned.m16n8k8.row.col.f32.tf32.tf32.f32 "
                        "{%0,%1,%2,%3}, {%4,%5,%6,%7}, {%8,%9}, {%0,%1,%2,%3};"
                        : "+f"(acc[mi][ni][0]), "+f"(acc[mi][ni][1]),
                          "+f"(acc[mi][ni][2]), "+f"(acc[mi][ni][3])
                        : "r"(a[mi][0]), "r"(a[mi][1]), "r"(a[mi][2]), "r"(a[mi][3]),
                          "r"(b[ni][0]), "r"(b[ni][1]));
                }
        }
    }

    // Epilogue: bias (+ GELU), float2 stores
#pragma unroll
    for (int mi = 0; mi < 4; mi++) {
#pragma unroll
        for (int ni = 0; ni < 4; ni++) {
            int col = n0 + wc + ni * 8 + qc * 2;
            float b0 = bias[col], b1 = bias[col + 1];
#pragma unroll
            for (int half = 0; half < 2; half++) {
                int row = m0 + wr + mi * 16 + qr + half * 8;
                float v0 = acc[mi][ni][half * 2 + 0] + b0;
                float v1 = acc[mi][ni][half * 2 + 1] + b1;
                if (ACT == 1) {
                    v0 = 0.5f * v0 * (1.f + erff(v0 * 0.70710678118654752f));
                    v1 = 0.5f * v1 * (1.f + erff(v1 * 0.70710678118654752f));
                }
                float2 o; o.x = v0; o.y = v1;
                *reinterpret_cast<float2*>(C + (size_t)row * N + col) = o;
            }
        }
    }
}

// ---------------------------------------------------------------------------
// Attention scores: per (b,h): S_out = scale * Q K^T + mask_bias
// ---------------------------------------------------------------------------
__global__ __launch_bounds__(256) void attn_scores_kernel(
    const float* __restrict__ qkv, const int* __restrict__ mask,
    float* __restrict__ attn) {
    const int bh = blockIdx.z, b = bh >> 3, h = bh & 7;
    const float* qb = qkv + (size_t)b * TS * QKVW + h * THD;
    const float* kb = qb + TE;  // k block offset
    __shared__ float Qs[16][64];
    __shared__ float Ks[16][64];
    const int t = threadIdx.x, tx = t & 15, ty = t >> 4;
    const int lrow = t >> 2;          // 0..63
    const int lq = (t & 3) << 2;      // 0,4,8,12
    const int m0 = blockIdx.y * 64, n0 = blockIdx.x * 64;
    float c[4][4] = {};
    for (int k0 = 0; k0 < THD; k0 += 16) {
        float4 q4 = *reinterpret_cast<const float4*>(qb + (size_t)(m0 + lrow) * QKVW + k0 + lq);
        float4 k4 = *reinterpret_cast<const float4*>(kb + (size_t)(n0 + lrow) * QKVW + k0 + lq);
        __syncthreads();
        Qs[lq + 0][lrow] = q4.x; Qs[lq + 1][lrow] = q4.y;
        Qs[lq + 2][lrow] = q4.z; Qs[lq + 3][lrow] = q4.w;
        Ks[lq + 0][lrow] = k4.x; Ks[lq + 1][lrow] = k4.y;
        Ks[lq + 2][lrow] = k4.z; Ks[lq + 3][lrow] = k4.w;
        __syncthreads();
#pragma unroll
        for (int kk = 0; kk < 16; kk++) {
            float ar[4], br[4];
#pragma unroll
            for (int i = 0; i < 4; i++) ar[i] = Qs[kk][ty * 4 + i];
#pragma unroll
            for (int j = 0; j < 4; j++) br[j] = Ks[kk][tx * 4 + j];
#pragma unroll
            for (int i = 0; i < 4; i++)
#pragma unroll
                for (int j = 0; j < 4; j++) c[i][j] = fmaf(ar[i], br[j], c[i][j]);
        }
    }
    float* out = attn + (size_t)bh * TS * TS;
    const float scale = 0.125f;  // 1/sqrt(64)
#pragma unroll
    for (int i = 0; i < 4; i++) {
        int qi = m0 + ty * 4 + i;
#pragma unroll
        for (int j = 0; j < 4; j++) {
            int kj = n0 + tx * 4 + j;
            float mb = (mask[b * TS + kj] == 0) ? -1e30f : 0.f;
            out[(size_t)qi * TS + kj] = c[i][j] * scale + mb;
        }
    }
}

// ---------------------------------------------------------------------------
// Row softmax in-place over 512 keys. 1 block/row, 128 threads, float4.
// ---------------------------------------------------------------------------
__global__ __launch_bounds__(128) void softmax_kernel(float* __restrict__ attn) {
    float* row = attn + (size_t)blockIdx.x * TS;
    const int t = threadIdx.x;
    float4 v = reinterpret_cast<float4*>(row)[t];
    float m = fmaxf(fmaxf(v.x, v.y), fmaxf(v.z, v.w));
#pragma unroll
    for (int o = 16; o; o >>= 1) m = fmaxf(m, __shfl_xor_sync(0xFFFFFFFFu, m, o));
    __shared__ float sm[4], ss[4];
    if ((t & 31) == 0) sm[t >> 5] = m;
    __syncthreads();
    m = fmaxf(fmaxf(sm[0], sm[1]), fmaxf(sm[2], sm[3]));
    v.x = __expf(v.x - m); v.y = __expf(v.y - m);
    v.z = __expf(v.z - m); v.w = __expf(v.w - m);
    float s = v.x + v.y + v.z + v.w;
#pragma unroll
    for (int o = 16; o; o >>= 1) s += __shfl_xor_sync(0xFFFFFFFFu, s, o);
    if ((t & 31) == 0) ss[t >> 5] = s;
    __syncthreads();
    s = ss[0] + ss[1] + ss[2] + ss[3];
    float inv = 1.f / s;
    v.x *= inv; v.y *= inv; v.z *= inv; v.w *= inv;
    reinterpret_cast<float4*>(row)[t] = v;
}

// ---------------------------------------------------------------------------
// AV: per (b,h): O[S,64] = P[S,S] @ V[S,64], scattered to concat layout.
// ---------------------------------------------------------------------------
__global__ __launch_bounds__(256) void attn_av_kernel(
    const float* __restrict__ attn, const float* __restrict__ qkv,
    float* __restrict__ outx) {
    const int bh = blockIdx.y, b = bh >> 3, h = bh & 7;
    const float* P = attn + (size_t)bh * TS * TS;
    const float* vb = qkv + (size_t)b * TS * QKVW + 2 * TE + h * THD;
    __shared__ float Ps[16][64];
    __shared__ float Vs[16][64];
    const int t = threadIdx.x, tx = t & 15, ty = t >> 4;
    const int m0 = blockIdx.x * 64;
    const int prow = t >> 2, pq = (t & 3) << 2;     // P: 64 rows x 16 k
    const int vrow = t >> 4, vq = (t & 15) << 2;    // V: 16 rows x 64 d
    float c[4][4] = {};
    for (int k0 = 0; k0 < TS; k0 += 16) {
        float4 p4 = *reinterpret_cast<const float4*>(P + (size_t)(m0 + prow) * TS + k0 + pq);
        float4 v4 = *reinterpret_cast<const float4*>(vb + (size_t)(k0 + vrow) * QKVW + vq);
        __syncthreads();
        Ps[pq + 0][prow] = p4.x; Ps[pq + 1][prow] = p4.y;
        Ps[pq + 2][prow] = p4.z; Ps[pq + 3][prow] = p4.w;
        Vs[vrow][vq + 0] = v4.x; Vs[vrow][vq + 1] = v4.y;
        Vs[vrow][vq + 2] = v4.z; Vs[vrow][vq + 3] = v4.w;
        __syncthreads();
#pragma unroll
        for (int kk = 0; kk < 16; kk++) {
            float ar[4], br[4];
#pragma unroll
            for (int i = 0; i < 4; i++) ar[i] = Ps[kk][ty * 4 + i];
#pragma unroll
            for (int j = 0; j < 4; j++) br[j] = Vs[kk][tx * 4 + j];
#pragma unroll
            for (int i = 0; i < 4; i++)
#pragma unroll
                for (int j = 0; j < 4; j++) c[i][j] = fmaf(ar[i], br[j], c[i][j]);
        }
    }
#pragma unroll
    for (int i = 0; i < 4; i++) {
        int qi = m0 + ty * 4 + i;
        float* o = outx + ((size_t)b * TS + qi) * TE + h * THD + tx * 4;
#pragma unroll
        for (int j = 0; j < 4; j++) o[j] = c[i][j];
    }
}

// ---------------------------------------------------------------------------
// Fused residual + LayerNorm: x = LN(x + y) * g + b. 1 block/token, 128 thr.
// ---------------------------------------------------------------------------
__global__ __launch_bounds__(128) void add_ln_kernel(
    float* __restrict__ x, const float* __restrict__ y,
    const float* __restrict__ g, const float* __restrict__ bb) {
    const size_t row = blockIdx.x;
    const int t = threadIdx.x;
    float4 xv = reinterpret_cast<float4*>(x + row * TE)[t];
    float4 yv = reinterpret_cast<const float4*>(y + row * TE)[t];
    float4 s;
    s.x = xv.x + yv.x; s.y = xv.y + yv.y; s.z = xv.z + yv.z; s.w = xv.w + yv.w;
    float sum = s.x + s.y + s.z + s.w;
    float sq = s.x * s.x + s.y * s.y + s.z * s.z + s.w * s.w;
#pragma unroll
    for (int o = 16; o; o >>= 1) {
        sum += __shfl_xor_sync(0xFFFFFFFFu, sum, o);
        sq  += __shfl_xor_sync(0xFFFFFFFFu, sq, o);
    }
    __shared__ float s1[4], s2[4];
    if ((t & 31) == 0) { s1[t >> 5] = sum; s2[t >> 5] = sq; }
    __syncthreads();
    sum = s1[0] + s1[1] + s1[2] + s1[3];
    sq  = s2[0] + s2[1] + s2[2] + s2[3];
    const float mean = sum * (1.f / TE);
    const float var = sq * (1.f / TE) - mean * mean;
    const float rstd = rsqrtf(var + 1e-5f);
    float4 gv = reinterpret_cast<const float4*>(g)[t];
    float4 bv = reinterpret_cast<const float4*>(bb)[t];
    float4 o;
    o.x = (s.x - mean) * rstd * gv.x + bv.x;
    o.y = (s.y - mean) * rstd * gv.y + bv.y;
    o.z = (s.z - mean) * rstd * gv.z + bv.z;
    o.w = (s.w - mean) * rstd * gv.w + bv.w;
    reinterpret_cast<float4*>(x + row * TE)[t] = o;
}

// ---------------------------------------------------------------------------
// CLS head: logits[b][c] = x[b*S] . cls_w[c] + cls_b[c]
// ---------------------------------------------------------------------------
__global__ void cls_kernel(const float* __restrict__ x, const float* __restrict__ w,
                           const float* __restrict__ cb, float* __restrict__ out) {
    int t = threadIdx.x;
    if (t >= TB * 2) return;
    int b = t >> 1, c = t & 1;
    const float* xr = x + (size_t)b * TS * TE;
    const float* wr = w + c * TE;
    float s = cb[c];
    for (int e = 0; e < TE; e++) s = fmaf(xr[e], wr[e], s);
    out[b * 2 + c] = s;
}

// ---------------------------------------------------------------------------
extern "C" void kernel_launch(void* const* d_in, const int* in_sizes, int n_in,
                              void* d_out, int out_size) {
    const int*   ids  = (const int*)d_in[0];
    const int*   mask = (const int*)d_in[1];
    const float* emb  = (const float*)d_in[2];
    const float* pos  = (const float*)d_in[3];
    const float* ipw  = (const float*)d_in[4];
    const float* ipb  = (const float*)d_in[5];
    const float* opw  = (const float*)d_in[6];
    const float* opb  = (const float*)d_in[7];
    const float* l1g  = (const float*)d_in[8];
    const float* l1b  = (const float*)d_in[9];
    const float* l2g  = (const float*)d_in[10];
    const float* l2b  = (const float*)d_in[11];
    const float* f1w  = (const float*)d_in[12];
    const float* f1b  = (const float*)d_in[13];
    const float* f2w  = (const float*)d_in[14];
    const float* f2b  = (const float*)d_in[15];
    const float* cw   = (const float*)d_in[16];
    const float* cb   = (const float*)d_in[17];
    float* out = (float*)d_out;
    float* attn_base = out + TB * 2;  // logits first, then [L,B,NH,S,S] attn

    float *x, *qkv, *att, *y, *hb;
    cudaGetSymbolAddress((void**)&x,   g_x);
    cudaGetSymbolAddress((void**)&qkv, g_qkv);
    cudaGetSymbolAddress((void**)&att, g_att);
    cudaGetSymbolAddress((void**)&y,   g_y);
    cudaGetSymbolAddress((void**)&hb,  g_h);

    embed_kernel<<<(TT * 128) / 256, 256>>>(ids, emb, pos, x);

    for (int l = 0; l < TL; l++) {
        // QKV projection: [TT,1536]
        tgemm_kernel<0><<<dim3(QKVW / 128, TT / 128), 256>>>(
            x, ipw + (size_t)l * QKVW * TE, ipb + l * QKVW, qkv, QKVW, TE);

        float* attn_l = attn_base + (size_t)l * TB * TNH * TS * TS;
        attn_scores_kernel<<<dim3(8, 8, TB * TNH), 256>>>(qkv, mask, attn_l);
        softmax_kernel<<<TB * TNH * TS, 128>>>(attn_l);
        attn_av_kernel<<<dim3(8, TB * TNH), 256>>>(attn_l, qkv, att);

        // out projection
        tgemm_kernel<0><<<dim3(TE / 128, TT / 128), 256>>>(
            att, opw + (size_t)l * TE * TE, opb + l * TE, y, TE, TE);
        add_ln_kernel<<<TT, 128>>>(x, y, l1g + l * TE, l1b + l * TE);

        // FFN
        tgemm_kernel<1><<<dim3(4 * TE / 128, TT / 128), 256>>>(
            x, f1w + (size_t)l * 4 * TE * TE, f1b + l * 4 * TE, hb, 4 * TE, TE);
        tgemm_kernel<0><<<dim3(TE / 128, TT / 128), 256>>>(
            hb, f2w + (size_t)l * TE * 4 * TE, f2b + l * TE, y, TE, 4 * TE);
        add_ln_kernel<<<TT, 128>>>(x, y, l2g + l * TE, l2b + l * TE);
    }

    cls_kernel<<<1, 64>>>(x, cw, cb, out);
}

// round 3
// speedup vs baseline: 2.8476x; 1.3119x over previous
#include <cuda_runtime.h>
#include <cuda_bf16.h>
#include <cstdint>
#include <math.h>

// Problem constants
#define TB 32      // batch
#define TS 512     // seq len
#define TE 512     // d_model
#define THD 64     // head dim
#define TNH 8      // heads
#define TL 3       // layers
#define TT (TB*TS) // tokens = 16384
#define QKVW 1536  // 3*E

// Scratch (device globals; allocation-free contract)
__device__ float g_x[(size_t)TT * TE];       // running hidden   32 MB
__device__ float g_qkv[(size_t)TT * QKVW];   // qkv              96 MB
__device__ float g_att[(size_t)TT * TE];     // attn concat out  32 MB
__device__ float g_y[(size_t)TT * TE];       // gemm out         32 MB
__device__ float g_h[(size_t)TT * 4 * TE];   // ffn hidden      128 MB

__device__ __forceinline__ uint32_t f2tf32(float x) {
    uint32_t u;
    asm("cvt.rna.tf32.f32 %0, %1;" : "=r"(u) : "f"(x));
    return u;
}

#define MMA_TF32(d, a, b)                                                     \
    asm volatile(                                                             \
        "mma.sync.aligned.m16n8k8.row.col.f32.tf32.tf32.f32 "                 \
        "{%0,%1,%2,%3}, {%4,%5,%6,%7}, {%8,%9}, {%0,%1,%2,%3};"               \
        : "+f"(d[0]), "+f"(d[1]), "+f"(d[2]), "+f"(d[3])                      \
        : "r"(a[0]), "r"(a[1]), "r"(a[2]), "r"(a[3]), "r"(b[0]), "r"(b[1]))

// ---------------------------------------------------------------------------
// Embedding: x[t] = emb[ids[t]] + pos[t % S]
// ---------------------------------------------------------------------------
__global__ __launch_bounds__(256) void embed_kernel(
    const int* __restrict__ ids, const float* __restrict__ emb,
    const float* __restrict__ pos, float* __restrict__ x) {
    int idx = blockIdx.x * blockDim.x + threadIdx.x;
    int token = idx >> 7;
    int c = idx & 127;
    float4 e = reinterpret_cast<const float4*>(emb)[(size_t)ids[token] * 128 + c];
    float4 p = reinterpret_cast<const float4*>(pos)[(size_t)(token & (TS - 1)) * 128 + c];
    float4 o;
    o.x = e.x + p.x; o.y = e.y + p.y; o.z = e.z + p.z; o.w = e.w + p.w;
    reinterpret_cast<float4*>(x)[idx] = o;
}

// ---------------------------------------------------------------------------
// TF32 tensor-core GEMM: C[M,N] = A[M,K] @ W[N,K]^T + bias[N], optional GELU.
// Block 128x128, ktile 32, 256 threads, warp tile 64x32. Software-pipelined:
// next k-tile's global loads are issued before the current tile's mma loop.
// ---------------------------------------------------------------------------
#define SPITCH 36

template <int ACT>
__global__ __launch_bounds__(256) void tgemm_kernel(
    const float* __restrict__ A, const float* __restrict__ W,
    const float* __restrict__ bias, float* __restrict__ C,
    int N, int K) {
    __shared__ uint32_t As[128 * SPITCH];
    __shared__ uint32_t Ws[128 * SPITCH];

    const int t = threadIdx.x;
    const int lane = t & 31;
    const int warp = t >> 5;
    const int wr = (warp >> 2) * 64;
    const int wc = (warp & 3) * 32;
    const int qr = lane >> 2;
    const int qc = lane & 3;

    const int m0 = blockIdx.y * 128;
    const int n0 = blockIdx.x * 128;

    const int lrow = t >> 3;            // 0..31 base row for loads (4 rows apart? no: f4)
    (void)lrow;

    float acc[4][4][4];
#pragma unroll
    for (int i = 0; i < 4; i++)
#pragma unroll
        for (int j = 0; j < 4; j++)
#pragma unroll
            for (int r = 0; r < 4; r++) acc[i][j][r] = 0.f;

    float4 av[4], wv[4];
    // preload first k-tile
#pragma unroll
    for (int i = 0; i < 4; i++) {
        int f4 = t + 256 * i;
        int row = f4 >> 3, kq = (f4 & 7) * 4;
        av[i] = *reinterpret_cast<const float4*>(A + (size_t)(m0 + row) * K + kq);
        wv[i] = *reinterpret_cast<const float4*>(W + (size_t)(n0 + row) * K + kq);
    }

    for (int k0 = 0; k0 < K; k0 += 32) {
        __syncthreads();
#pragma unroll
        for (int i = 0; i < 4; i++) {
            int f4 = t + 256 * i;
            int row = f4 >> 3, kq = (f4 & 7) * 4;
            uint32_t* as = &As[row * SPITCH + kq];
            as[0] = f2tf32(av[i].x); as[1] = f2tf32(av[i].y);
            as[2] = f2tf32(av[i].z); as[3] = f2tf32(av[i].w);
            uint32_t* ws = &Ws[row * SPITCH + kq];
            ws[0] = f2tf32(wv[i].x); ws[1] = f2tf32(wv[i].y);
            ws[2] = f2tf32(wv[i].z); ws[3] = f2tf32(wv[i].w);
        }
        __syncthreads();

        // issue next tile's loads; latency hides under the mma loop below
        if (k0 + 32 < K) {
#pragma unroll
            for (int i = 0; i < 4; i++) {
                int f4 = t + 256 * i;
                int row = f4 >> 3, kq = (f4 & 7) * 4;
                av[i] = *reinterpret_cast<const float4*>(A + (size_t)(m0 + row) * K + k0 + 32 + kq);
                wv[i] = *reinterpret_cast<const float4*>(W + (size_t)(n0 + row) * K + k0 + 32 + kq);
            }
        }

#pragma unroll
        for (int kk = 0; kk < 32; kk += 8) {
            uint32_t a[4][4], b[4][2];
#pragma unroll
            for (int mi = 0; mi < 4; mi++) {
                const uint32_t* base = &As[(wr + mi * 16 + qr) * SPITCH + kk + qc];
                a[mi][0] = base[0];
                a[mi][1] = base[8 * SPITCH];
                a[mi][2] = base[4];
                a[mi][3] = base[8 * SPITCH + 4];
            }
#pragma unroll
            for (int ni = 0; ni < 4; ni++) {
                const uint32_t* base = &Ws[(wc + ni * 8 + qr) * SPITCH + kk + qc];
                b[ni][0] = base[0];
                b[ni][1] = base[4];
            }
#pragma unroll
            for (int mi = 0; mi < 4; mi++)
#pragma unroll
                for (int ni = 0; ni < 4; ni++) MMA_TF32(acc[mi][ni], a[mi], b[ni]);
        }
    }

#pragma unroll
    for (int mi = 0; mi < 4; mi++) {
#pragma unroll
        for (int ni = 0; ni < 4; ni++) {
            int col = n0 + wc + ni * 8 + qc * 2;
            float b0 = bias[col], b1 = bias[col + 1];
#pragma unroll
            for (int half = 0; half < 2; half++) {
                int row = m0 + wr + mi * 16 + qr + half * 8;
                float v0 = acc[mi][ni][half * 2 + 0] + b0;
                float v1 = acc[mi][ni][half * 2 + 1] + b1;
                if (ACT == 1) {
                    v0 = 0.5f * v0 * (1.f + erff(v0 * 0.70710678118654752f));
                    v1 = 0.5f * v1 * (1.f + erff(v1 * 0.70710678118654752f));
                }
                float2 o; o.x = v0; o.y = v1;
                *reinterpret_cast<float2*>(C + (size_t)row * N + col) = o;
            }
        }
    }
}

// ---------------------------------------------------------------------------
// Fused attention scores + softmax (TF32 tensor cores).
// Per block: 64 query rows x all 512 keys for one (b,h).
// grid (8 mtiles, B*NH), block 256 = 8 warps; warp w owns key cols
// {chunk*64 + w*8 .. +8} over 8 key chunks of 64.
// Writes normalized probabilities directly (single pass over attn tensor).
// ---------------------------------------------------------------------------
#define APITCH 68

__global__ __launch_bounds__(256) void attn_fused_kernel(
    const float* __restrict__ qkv, const int* __restrict__ mask,
    float* __restrict__ attn) {
    __shared__ uint32_t Qs[64 * APITCH];
    __shared__ uint32_t Ks[64 * APITCH];
    __shared__ float biasS[512];
    __shared__ float red[64 * 9];

    const int t = threadIdx.x, lane = t & 31, warp = t >> 5;
    const int qr = lane >> 2, qc = lane & 3;
    const int bh = blockIdx.y, b = bh >> 3, h = bh & 7;
    const int m0 = blockIdx.x * 64;
    const float* qb = qkv + (size_t)b * TS * QKVW + h * THD;
    const float* kb = qb + TE;

    for (int i = t; i < 512; i += 256)
        biasS[i] = (mask[b * TS + i] == 0) ? -1e30f : 0.f;

    // Load Q tile 64x64 -> Qs (tf32)
#pragma unroll
    for (int i = 0; i < 4; i++) {
        int f4 = t + 256 * i;
        int row = f4 >> 4, kq = (f4 & 15) * 4;
        float4 q4 = *reinterpret_cast<const float4*>(qb + (size_t)(m0 + row) * QKVW + kq);
        uint32_t* s = &Qs[row * APITCH + kq];
        s[0] = f2tf32(q4.x); s[1] = f2tf32(q4.y);
        s[2] = f2tf32(q4.z); s[3] = f2tf32(q4.w);
    }

    float acc[8][4][4];  // [key chunk][mi][frag]
#pragma unroll
    for (int c = 0; c < 8; c++)
#pragma unroll
        for (int mi = 0; mi < 4; mi++)
#pragma unroll
            for (int r = 0; r < 4; r++) acc[c][mi][r] = 0.f;

    // preload K chunk 0
    float4 kv[4];
#pragma unroll
    for (int i = 0; i < 4; i++) {
        int f4 = t + 256 * i;
        int row = f4 >> 4, kq = (f4 & 15) * 4;
        kv[i] = *reinterpret_cast<const float4*>(kb + (size_t)row * QKVW + kq);
    }

    for (int c = 0; c < 8; c++) {
        __syncthreads();
#pragma unroll
        for (int i = 0; i < 4; i++) {
            int f4 = t + 256 * i;
            int row = f4 >> 4, kq = (f4 & 15) * 4;
            uint32_t* s = &Ks[row * APITCH + kq];
            s[0] = f2tf32(kv[i].x); s[1] = f2tf32(kv[i].y);
            s[2] = f2tf32(kv[i].z); s[3] = f2tf32(kv[i].w);
        }
        __syncthreads();
        if (c < 7) {
#pragma unroll
            for (int i = 0; i < 4; i++) {
                int f4 = t + 256 * i;
                int row = f4 >> 4, kq = (f4 & 15) * 4;
                kv[i] = *reinterpret_cast<const float4*>(kb + (size_t)((c + 1) * 64 + row) * QKVW + kq);
            }
        }
#pragma unroll
        for (int kk = 0; kk < 64; kk += 8) {
            uint32_t a[4][4], bf[2];
#pragma unroll
            for (int mi = 0; mi < 4; mi++) {
                const uint32_t* base = &Qs[(mi * 16 + qr) * APITCH + kk + qc];
                a[mi][0] = base[0];
                a[mi][1] = base[8 * APITCH];
                a[mi][2] = base[4];
                a[mi][3] = base[8 * APITCH + 4];
            }
            {
                const uint32_t* base = &Ks[(warp * 8 + qr) * APITCH + kk + qc];
                bf[0] = base[0];
                bf[1] = base[4];
            }
#pragma unroll
            for (int mi = 0; mi < 4; mi++) MMA_TF32(acc[c][mi], a[mi], bf);
        }
    }

    // ---- softmax over 512 keys per row ----
    float bm[4][2], bs[4][2];
    const float scale = 0.125f;
    // pass 1: scale + mask bias + row max
#pragma unroll
    for (int mi = 0; mi < 4; mi++) {
#pragma unroll
        for (int h2 = 0; h2 < 2; h2++) {
            float m = -3.4e38f;
#pragma unroll
            for (int c = 0; c < 8; c++) {
                int col = c * 64 + warp * 8 + qc * 2;
                float v0 = acc[c][mi][2 * h2 + 0] * scale + biasS[col];
                float v1 = acc[c][mi][2 * h2 + 1] * scale + biasS[col + 1];
                acc[c][mi][2 * h2 + 0] = v0;
                acc[c][mi][2 * h2 + 1] = v1;
                m = fmaxf(m, fmaxf(v0, v1));
            }
            m = fmaxf(m, __shfl_xor_sync(0xFFFFFFFFu, m, 1));
            m = fmaxf(m, __shfl_xor_sync(0xFFFFFFFFu, m, 2));
            bm[mi][h2] = m;
        }
    }
    if (qc == 0) {
#pragma unroll
        for (int mi = 0; mi < 4; mi++)
#pragma unroll
            for (int h2 = 0; h2 < 2; h2++)
                red[(mi * 16 + qr + h2 * 8) * 9 + warp] = bm[mi][h2];
    }
    __syncthreads();
#pragma unroll
    for (int mi = 0; mi < 4; mi++)
#pragma unroll
        for (int h2 = 0; h2 < 2; h2++) {
            int row = mi * 16 + qr + h2 * 8;
            float m = red[row * 9 + 0];
#pragma unroll
            for (int w2 = 1; w2 < 8; w2++) m = fmaxf(m, red[row * 9 + w2]);
            bm[mi][h2] = m;
        }
    __syncthreads();
    // pass 2: exp + row sum
#pragma unroll
    for (int mi = 0; mi < 4; mi++) {
#pragma unroll
        for (int h2 = 0; h2 < 2; h2++) {
            float m = bm[mi][h2];
            float s = 0.f;
#pragma unroll
            for (int c = 0; c < 8; c++) {
                float e0 = __expf(acc[c][mi][2 * h2 + 0] - m);
                float e1 = __expf(acc[c][mi][2 * h2 + 1] - m);
                acc[c][mi][2 * h2 + 0] = e0;
                acc[c][mi][2 * h2 + 1] = e1;
                s += e0 + e1;
            }
            s += __shfl_xor_sync(0xFFFFFFFFu, s, 1);
            s += __shfl_xor_sync(0xFFFFFFFFu, s, 2);
            bs[mi][h2] = s;
        }
    }
    if (qc == 0) {
#pragma unroll
        for (int mi = 0; mi < 4; mi++)
#pragma unroll
            for (int h2 = 0; h2 < 2; h2++)
                red[(mi * 16 + qr + h2 * 8) * 9 + warp] = bs[mi][h2];
    }
    __syncthreads();
#pragma unroll
    for (int mi = 0; mi < 4; mi++)
#pragma unroll
        for (int h2 = 0; h2 < 2; h2++) {
            int row = mi * 16 + qr + h2 * 8;
            float s = 0.f;
#pragma unroll
            for (int w2 = 0; w2 < 8; w2++) s += red[row * 9 + w2];
            float inv = 1.f / s;
            float* orow = attn + ((size_t)bh * TS + m0 + row) * TS;
#pragma unroll
            for (int c = 0; c < 8; c++) {
                int col = c * 64 + warp * 8 + qc * 2;
                float2 o;
                o.x = acc[c][mi][2 * h2 + 0] * inv;
                o.y = acc[c][mi][2 * h2 + 1] * inv;
                *reinterpret_cast<float2*>(orow + col) = o;
            }
        }
}

// ---------------------------------------------------------------------------
// AV on tensor cores: per (b,h): O[64,64] tile = P[64,512] @ V[512,64].
// grid (8 mtiles, B*NH), block 256 = 8 warps; warp (w&3) owns 16 rows,
// (w>>2) owns 32 of the 64 head dims. V's natural [key][dim] layout is the
// mma B operand layout — indexed loads, no transpose.
// ---------------------------------------------------------------------------
__global__ __launch_bounds__(256) void attn_av_tc_kernel(
    const float* __restrict__ attn, const float* __restrict__ qkv,
    float* __restrict__ outx) {
    __shared__ uint32_t Ps[64 * APITCH];
    __shared__ uint32_t Vs[64 * APITCH];

    const int t = threadIdx.x, lane = t & 31, warp = t >> 5;
    const int qr = lane >> 2, qc = lane & 3;
    const int bh = blockIdx.y, b = bh >> 3, h = bh & 7;
    const int m0 = blockIdx.x * 64;
    const int wr = (warp & 3) * 16;
    const int wc = (warp >> 2) * 32;
    const float* P = attn + (size_t)bh * TS * TS;
    const float* vb = qkv + (size_t)b * TS * QKVW + 2 * TE + h * THD;

    float acc[4][4] = {};  // [ni][frag]

    float4 pv[4], vv[4];
#pragma unroll
    for (int i = 0; i < 4; i++) {
        int f4 = t + 256 * i;
        int row = f4 >> 4, kq = (f4 & 15) * 4;
        pv[i] = *reinterpret_cast<const float4*>(P + (size_t)(m0 + row) * TS + kq);
        vv[i] = *reinterpret_cast<const float4*>(vb + (size_t)row * QKVW + kq);
    }

    for (int kc = 0; kc < 8; kc++) {
        __syncthreads();
#pragma unroll
        for (int i = 0; i < 4; i++) {
            int f4 = t + 256 * i;
            int row = f4 >> 4, kq = (f4 & 15) * 4;
            uint32_t* sp = &Ps[row * APITCH + kq];
            sp[0] = f2tf32(pv[i].x); sp[1] = f2tf32(pv[i].y);
            sp[2] = f2tf32(pv[i].z); sp[3] = f2tf32(pv[i].w);
            uint32_t* sv = &Vs[row * APITCH + kq];
            sv[0] = f2tf32(vv[i].x); sv[1] = f2tf32(vv[i].y);
            sv[2] = f2tf32(vv[i].z); sv[3] = f2tf32(vv[i].w);
        }
        __syncthreads();
        if (kc < 7) {
#pragma unroll
            for (int i = 0; i < 4; i++) {
                int f4 = t + 256 * i;
                int row = f4 >> 4, kq = (f4 & 15) * 4;
                pv[i] = *reinterpret_cast<const float4*>(P + (size_t)(m0 + row) * TS + (kc + 1) * 64 + kq);
                vv[i] = *reinterpret_cast<const float4*>(vb + (size_t)((kc + 1) * 64 + row) * QKVW + kq);
            }
        }
#pragma unroll
        for (int kk = 0; kk < 64; kk += 8) {
            uint32_t a[4], bf[4][2];
            {
                const uint32_t* base = &Ps[(wr + qr) * APITCH + kk + qc];
                a[0] = base[0];
                a[1] = base[8 * APITCH];
                a[2] = base[4];
                a[3] = base[8 * APITCH + 4];
            }
#pragma unroll
            for (int ni = 0; ni < 4; ni++) {
                bf[ni][0] = Vs[(kk + qc) * APITCH + wc + ni * 8 + qr];
                bf[ni][1] = Vs[(kk + qc + 4) * APITCH + wc + ni * 8 + qr];
            }
#pragma unroll
            for (int ni = 0; ni < 4; ni++) MMA_TF32(acc[ni], a, bf[ni]);
        }
    }

#pragma unroll
    for (int ni = 0; ni < 4; ni++) {
#pragma unroll
        for (int h2 = 0; h2 < 2; h2++) {
            int row = m0 + wr + qr + h2 * 8;
            int col = wc + ni * 8 + qc * 2;
            float2 o;
            o.x = acc[ni][2 * h2 + 0];
            o.y = acc[ni][2 * h2 + 1];
            *reinterpret_cast<float2*>(outx + ((size_t)b * TS + row) * TE + h * THD + col) = o;
        }
    }
}

// ---------------------------------------------------------------------------
// Fused residual + LayerNorm: x = LN(x + y) * g + b. 1 block/token, 128 thr.
// ---------------------------------------------------------------------------
__global__ __launch_bounds__(128) void add_ln_kernel(
    float* __restrict__ x, const float* __restrict__ y,
    const float* __restrict__ g, const float* __restrict__ bb) {
    const size_t row = blockIdx.x;
    const int t = threadIdx.x;
    float4 xv = reinterpret_cast<float4*>(x + row * TE)[t];
    float4 yv = reinterpret_cast<const float4*>(y + row * TE)[t];
    float4 s;
    s.x = xv.x + yv.x; s.y = xv.y + yv.y; s.z = xv.z + yv.z; s.w = xv.w + yv.w;
    float sum = s.x + s.y + s.z + s.w;
    float sq = s.x * s.x + s.y * s.y + s.z * s.z + s.w * s.w;
#pragma unroll
    for (int o = 16; o; o >>= 1) {
        sum += __shfl_xor_sync(0xFFFFFFFFu, sum, o);
        sq  += __shfl_xor_sync(0xFFFFFFFFu, sq, o);
    }
    __shared__ float s1[4], s2[4];
    if ((t & 31) == 0) { s1[t >> 5] = sum; s2[t >> 5] = sq; }
    __syncthreads();
    sum = s1[0] + s1[1] + s1[2] + s1[3];
    sq  = s2[0] + s2[1] + s2[2] + s2[3];
    const float mean = sum * (1.f / TE);
    const float var = sq * (1.f / TE) - mean * mean;
    const float rstd = rsqrtf(var + 1e-5f);
    float4 gv = reinterpret_cast<const float4*>(g)[t];
    float4 bv = reinterpret_cast<const float4*>(bb)[t];
    float4 o;
    o.x = (s.x - mean) * rstd * gv.x + bv.x;
    o.y = (s.y - mean) * rstd * gv.y + bv.y;
    o.z = (s.z - mean) * rstd * gv.z + bv.z;
    o.w = (s.w - mean) * rstd * gv.w + bv.w;
    reinterpret_cast<float4*>(x + row * TE)[t] = o;
}

// ---------------------------------------------------------------------------
// CLS head
// ---------------------------------------------------------------------------
__global__ void cls_kernel(const float* __restrict__ x, const float* __restrict__ w,
                           const float* __restrict__ cb, float* __restrict__ out) {
    int t = threadIdx.x;
    if (t >= TB * 2) return;
    int b = t >> 1, c = t & 1;
    const float* xr = x + (size_t)b * TS * TE;
    const float* wr = w + c * TE;
    float s = cb[c];
    for (int e = 0; e < TE; e++) s = fmaf(xr[e], wr[e], s);
    out[b * 2 + c] = s;
}

// ---------------------------------------------------------------------------
extern "C" void kernel_launch(void* const* d_in, const int* in_sizes, int n_in,
                              void* d_out, int out_size) {
    const int*   ids  = (const int*)d_in[0];
    const int*   mask = (const int*)d_in[1];
    const float* emb  = (const float*)d_in[2];
    const float* pos  = (const float*)d_in[3];
    const float* ipw  = (const float*)d_in[4];
    const float* ipb  = (const float*)d_in[5];
    const float* opw  = (const float*)d_in[6];
    const float* opb  = (const float*)d_in[7];
    const float* l1g  = (const float*)d_in[8];
    const float* l1b  = (const float*)d_in[9];
    const float* l2g  = (const float*)d_in[10];
    const float* l2b  = (const float*)d_in[11];
    const float* f1w  = (const float*)d_in[12];
    const float* f1b  = (const float*)d_in[13];
    const float* f2w  = (const float*)d_in[14];
    const float* f2b  = (const float*)d_in[15];
    const float* cw   = (const float*)d_in[16];
    const float* cb   = (const float*)d_in[17];
    float* out = (float*)d_out;
    float* attn_base = out + TB * 2;  // logits first, then [L,B,NH,S,S] attn

    float *x, *qkv, *att, *y, *hb;
    cudaGetSymbolAddress((void**)&x,   g_x);
    cudaGetSymbolAddress((void**)&qkv, g_qkv);
    cudaGetSymbolAddress((void**)&att, g_att);
    cudaGetSymbolAddress((void**)&y,   g_y);
    cudaGetSymbolAddress((void**)&hb,  g_h);

    embed_kernel<<<(TT * 128) / 256, 256>>>(ids, emb, pos, x);

    for (int l = 0; l < TL; l++) {
        tgemm_kernel<0><<<dim3(QKVW / 128, TT / 128), 256>>>(
            x, ipw + (size_t)l * QKVW * TE, ipb + l * QKVW, qkv, QKVW, TE);

        float* attn_l = attn_base + (size_t)l * TB * TNH * TS * TS;
        attn_fused_kernel<<<dim3(8, TB * TNH), 256>>>(qkv, mask, attn_l);
        attn_av_tc_kernel<<<dim3(8, TB * TNH), 256>>>(attn_l, qkv, att);

        tgemm_kernel<0><<<dim3(TE / 128, TT / 128), 256>>>(
            att, opw + (size_t)l * TE * TE, opb + l * TE, y, TE, TE);
        add_ln_kernel<<<TT, 128>>>(x, y, l1g + l * TE, l1b + l * TE);

        tgemm_kernel<1><<<dim3(4 * TE / 128, TT / 128), 256>>>(
            x, f1w + (size_t)l * 4 * TE * TE, f1b + l * 4 * TE, hb, 4 * TE, TE);
        tgemm_kernel<0><<<dim3(TE / 128, TT / 128), 256>>>(
            hb, f2w + (size_t)l * TE * 4 * TE, f2b + l * TE, y, TE, 4 * TE);
        add_ln_kernel<<<TT, 128>>>(x, y, l2g + l * TE, l2b + l * TE);
    }

    cls_kernel<<<1, 64>>>(x, cw, cb, out);
}